// round 2
// baseline (speedup 1.0000x reference)
#include <cuda_runtime.h>
#include <math.h>

// ChamferLoss: bs=4, npts=4096, dim=3.
// dist^2(q, r) = ||q||^2 + (||r||^2 - 2 q.r)  -> inner loop = 3 packed FMAs per 2 refs.
// smem per block: SoA groups of 4 refs: [ -2rx*4 | -2ry*4 | -2rz*4 | ||r||^2*4 ] (64B/group).

#define NPTS 4096
#define BS   4
#define TPB  128
#define QPT  2                       // queries per thread
#define QTILE (TPB * QPT)            // 256 queries per block
#define NQT  (NPTS / QTILE)          // 16 query tiles
#define NBLK (NQT * BS * 2)          // 128 blocks == one balanced wave
#define SMEM_BYTES (NPTS * 4 * 4)    // 65536

__device__ float g_partial[NBLK];
__device__ unsigned int g_count = 0;

__device__ __forceinline__ unsigned long long bcast2(float f) {
    unsigned long long v;
    asm("mov.b64 %0, {%1, %1};" : "=l"(v) : "r"(__float_as_uint(f)));
    return v;
}
__device__ __forceinline__ void unpack2(unsigned long long v, float& a, float& b) {
    unsigned lo, hi;
    asm("mov.b64 {%0, %1}, %2;" : "=r"(lo), "=r"(hi) : "l"(v));
    a = __uint_as_float(lo); b = __uint_as_float(hi);
}

__global__ __launch_bounds__(TPB) void chamfer_kernel(
    const float* __restrict__ x, const float* __restrict__ y, float* __restrict__ out)
{
    extern __shared__ float s[];          // 16384 floats = 64KB
    __shared__ float red[4];
    __shared__ int   s_last;

    const int tid = threadIdx.x;
    const int qt  = blockIdx.x;
    const int b   = blockIdx.y;
    const int dir = blockIdx.z;           // 0: query=x ref=y ; 1: query=y ref=x

    const float* __restrict__ q  = dir ? y : x;
    const float* __restrict__ r  = dir ? x : y;
    const float* __restrict__ rb = r + (size_t)b * NPTS * 3;

    // Stage refs: -2r (SoA, 4-wide groups) and ||r||^2.
    #pragma unroll 4
    for (int i = tid; i < NPTS; i += TPB) {
        float rx = rb[3 * i + 0];
        float ry = rb[3 * i + 1];
        float rz = rb[3 * i + 2];
        float* base = s + ((i >> 2) << 4) + (i & 3);
        base[0]  = -2.0f * rx;
        base[4]  = -2.0f * ry;
        base[8]  = -2.0f * rz;
        base[12] = fmaf(rx, rx, fmaf(ry, ry, rz * rz));
    }

    // This thread's two query points.
    const int qi0 = qt * QTILE + tid;
    const int qi1 = qi0 + TPB;
    const float* qp0 = q + ((size_t)b * NPTS + qi0) * 3;
    const float* qp1 = q + ((size_t)b * NPTS + qi1) * 3;
    const float qx0 = qp0[0], qy0 = qp0[1], qz0 = qp0[2];
    const float qx1 = qp1[0], qy1 = qp1[1], qz1 = qp1[2];
    const float qsq0 = fmaf(qx0, qx0, fmaf(qy0, qy0, qz0 * qz0));
    const float qsq1 = fmaf(qx1, qx1, fmaf(qy1, qy1, qz1 * qz1));
    const unsigned long long bx0 = bcast2(qx0), by0 = bcast2(qy0), bz0 = bcast2(qz0);
    const unsigned long long bx1 = bcast2(qx1), by1 = bcast2(qy1), bz1 = bcast2(qz1);

    __syncthreads();

    unsigned sa = (unsigned)__cvta_generic_to_shared(s);
    float m0 = 3.402823466e+38f;
    float m1 = 3.402823466e+38f;

    #pragma unroll 4
    for (int g = 0; g < NPTS / 4; ++g, sa += 64) {
        unsigned long long X01, X23, Y01, Y23, Z01, Z23, H01, H23;
        asm("ld.shared.v2.u64 {%0,%1}, [%2];"      : "=l"(X01), "=l"(X23) : "r"(sa));
        asm("ld.shared.v2.u64 {%0,%1}, [%2+16];"   : "=l"(Y01), "=l"(Y23) : "r"(sa));
        asm("ld.shared.v2.u64 {%0,%1}, [%2+32];"   : "=l"(Z01), "=l"(Z23) : "r"(sa));
        asm("ld.shared.v2.u64 {%0,%1}, [%2+48];"   : "=l"(H01), "=l"(H23) : "r"(sa));

        unsigned long long t0, t1, u0, u1;
        // query 0
        asm("fma.rn.f32x2 %0, %1, %2, %3;" : "=l"(t0) : "l"(bx0), "l"(X01), "l"(H01));
        asm("fma.rn.f32x2 %0, %1, %2, %0;" : "+l"(t0) : "l"(by0), "l"(Y01));
        asm("fma.rn.f32x2 %0, %1, %2, %0;" : "+l"(t0) : "l"(bz0), "l"(Z01));
        asm("fma.rn.f32x2 %0, %1, %2, %3;" : "=l"(t1) : "l"(bx0), "l"(X23), "l"(H23));
        asm("fma.rn.f32x2 %0, %1, %2, %0;" : "+l"(t1) : "l"(by0), "l"(Y23));
        asm("fma.rn.f32x2 %0, %1, %2, %0;" : "+l"(t1) : "l"(bz0), "l"(Z23));
        // query 1
        asm("fma.rn.f32x2 %0, %1, %2, %3;" : "=l"(u0) : "l"(bx1), "l"(X01), "l"(H01));
        asm("fma.rn.f32x2 %0, %1, %2, %0;" : "+l"(u0) : "l"(by1), "l"(Y01));
        asm("fma.rn.f32x2 %0, %1, %2, %0;" : "+l"(u0) : "l"(bz1), "l"(Z01));
        asm("fma.rn.f32x2 %0, %1, %2, %3;" : "=l"(u1) : "l"(bx1), "l"(X23), "l"(H23));
        asm("fma.rn.f32x2 %0, %1, %2, %0;" : "+l"(u1) : "l"(by1), "l"(Y23));
        asm("fma.rn.f32x2 %0, %1, %2, %0;" : "+l"(u1) : "l"(bz1), "l"(Z23));

        float a0, a1, a2, a3;
        unpack2(t0, a0, a1); unpack2(t1, a2, a3);
        m0 = fminf(m0, fminf(fminf(a0, a1), fminf(a2, a3)));
        float c0, c1, c2, c3;
        unpack2(u0, c0, c1); unpack2(u1, c2, c3);
        m1 = fminf(m1, fminf(fminf(c0, c1), fminf(c2, c3)));
    }

    float v = sqrtf(1e-6f + qsq0 + m0) + sqrtf(1e-6f + qsq1 + m1);

    // Deterministic block sum.
    #pragma unroll
    for (int off = 16; off; off >>= 1)
        v += __shfl_down_sync(0xFFFFFFFFu, v, off);
    if ((tid & 31) == 0) red[tid >> 5] = v;
    __syncthreads();

    const int bid = (dir * BS + b) * NQT + qt;
    if (tid == 0) {
        g_partial[bid] = red[0] + red[1] + red[2] + red[3];
        __threadfence();
        unsigned old = atomicAdd(&g_count, 1u);
        s_last = (old == NBLK - 1) ? 1 : 0;
    }
    __syncthreads();

    // Last block finishes: fixed-order final reduction (deterministic), reset counter.
    if (s_last) {
        volatile float* gp = g_partial;
        float w = gp[tid];                 // NBLK == TPB == 128
        #pragma unroll
        for (int off = 16; off; off >>= 1)
            w += __shfl_down_sync(0xFFFFFFFFu, w, off);
        if ((tid & 31) == 0) red[tid >> 5] = w;
        __syncthreads();
        if (tid == 0) {
            out[0] = (red[0] + red[1] + red[2] + red[3]) * (1.0f / 16384.0f);
            g_count = 0;                   // self-reset for graph replay
        }
    }
}

extern "C" void kernel_launch(void* const* d_in, const int* in_sizes, int n_in,
                              void* d_out, int out_size)
{
    const float* x = (const float*)d_in[0];
    const float* y = (const float*)d_in[1];
    float* out = (float*)d_out;

    cudaFuncSetAttribute(chamfer_kernel,
                         cudaFuncAttributeMaxDynamicSharedMemorySize, SMEM_BYTES);
    chamfer_kernel<<<dim3(NQT, BS, 2), TPB, SMEM_BYTES>>>(x, y, out);
}